// round 12
// baseline (speedup 1.0000x reference)
#include <cuda_runtime.h>
#include <cuda_bf16.h>
#include <cstdint>
#include <math.h>

// ============================================================================
// Problem constants
// ============================================================================
namespace {
constexpr int kE = 1024;
constexpr int kD = 64;
constexpr int kB = 8;
constexpr int kS = 2048;
constexpr int kRows = kB * kS;  // 16384
constexpr float kShift = 16.0f;  // fixed softmax shift; scores ~N(0,1)
constexpr int kPitch = 144;      // smem K/V/B row pitch bytes (64 bf16 + pad)
constexpr int kAPitch = 80;      // proj A smem pitch bytes; MUST be 16B mult
                                 // (ldmatrix row addrs are 128-bit aligned)
// attn stage layout (bytes)
constexpr int kStageBytes = 4 * 64 * kPitch;  // 36864
constexpr int kOffKhi = 0, kOffKlo = 9216, kOffVhi = 18432, kOffVlo = 27648;
}

// bf16 split operands (hi + lo ~= fp32). 16B-aligned: accessed with
// uint4 / cp.async.16.
__device__ __align__(16) __nv_bfloat16 g_qhi[kRows * kD];
__device__ __align__(16) __nv_bfloat16 g_qlo[kRows * kD];
__device__ __align__(16) __nv_bfloat16 g_khi[kRows * kD];
__device__ __align__(16) __nv_bfloat16 g_klo[kRows * kD];
__device__ __align__(16) __nv_bfloat16 g_vhi[kRows * kD];
__device__ __align__(16) __nv_bfloat16 g_vlo[kRows * kD];
// pre-split weights, layout [w][k][n], w in {q,k,v}
__device__ __align__(16) __nv_bfloat16 g_whi[3 * kE * kD];
__device__ __align__(16) __nv_bfloat16 g_wlo[3 * kE * kD];

__device__ __forceinline__ void split_bf16(float x, unsigned short& h,
                                           unsigned short& l) {
  __nv_bfloat16 bh = __float2bfloat16_rn(x);
  h = __bfloat16_as_ushort(bh);
  float r = x - __bfloat162float(bh);
  l = __bfloat16_as_ushort(__float2bfloat16_rn(r));
}

__device__ __forceinline__ uint32_t smem_u32(const void* p) {
  uint32_t a;
  asm("{ .reg .u64 t; cvta.to.shared.u64 t, %1; cvt.u32.u64 %0, t; }"
      : "=r"(a) : "l"(p));
  return a;
}

// mma.sync m16n8k16 row.col f32 += bf16*bf16
__device__ __forceinline__ void mma_bf16(float* c, const uint32_t* a,
                                         uint32_t b0, uint32_t b1) {
  asm volatile(
      "mma.sync.aligned.m16n8k16.row.col.f32.bf16.bf16.f32 "
      "{%0,%1,%2,%3}, {%4,%5,%6,%7}, {%8,%9}, {%0,%1,%2,%3};\n"
      : "+f"(c[0]), "+f"(c[1]), "+f"(c[2]), "+f"(c[3])
      : "r"(a[0]), "r"(a[1]), "r"(a[2]), "r"(a[3]), "r"(b0), "r"(b1));
}
__device__ __forceinline__ void ldsm_x4(uint32_t* r, uint32_t addr) {
  asm volatile("ldmatrix.sync.aligned.m8n8.x4.shared.b16 {%0,%1,%2,%3}, [%4];"
               : "=r"(r[0]), "=r"(r[1]), "=r"(r[2]), "=r"(r[3]) : "r"(addr));
}
__device__ __forceinline__ void ldsm_x4_t(uint32_t* r, uint32_t addr) {
  asm volatile(
      "ldmatrix.sync.aligned.m8n8.x4.trans.shared.b16 {%0,%1,%2,%3}, [%4];"
      : "=r"(r[0]), "=r"(r[1]), "=r"(r[2]), "=r"(r[3]) : "r"(addr));
}
__device__ __forceinline__ void cp16(uint32_t s, const void* g) {
  asm volatile("cp.async.cg.shared.global [%0], [%1], 16;" ::"r"(s), "l"(g));
}
#define CP_COMMIT() asm volatile("cp.async.commit_group;" ::: "memory")
#define CP_WAIT(n) asm volatile("cp.async.wait_group %0;" ::"n"(n) : "memory")

// ============================================================================
// One-time W split: [w][k][n] fp32 -> bf16 hi/lo.
// ============================================================================
__global__ __launch_bounds__(256) void split_w_kernel(
    const float* __restrict__ Wq, const float* __restrict__ Wk,
    const float* __restrict__ Wv) {
  int idx4 = (blockIdx.x * 256 + threadIdx.x) * 4;  // grid 192 -> 196608 elems
  int w = idx4 >> 16, rem = idx4 & 65535;
  const float* Wp = (w == 0) ? Wq : (w == 1) ? Wk : Wv;
  float4 v = *(const float4*)(Wp + rem);
  unsigned short h[4], l[4];
  split_bf16(v.x, h[0], l[0]); split_bf16(v.y, h[1], l[1]);
  split_bf16(v.z, h[2], l[2]); split_bf16(v.w, h[3], l[3]);
  uint2 hv = {(uint32_t)h[0] | ((uint32_t)h[1] << 16),
              (uint32_t)h[2] | ((uint32_t)h[3] << 16)};
  uint2 lv = {(uint32_t)l[0] | ((uint32_t)l[1] << 16),
              (uint32_t)l[2] | ((uint32_t)l[3] << 16)};
  *(uint2*)((unsigned char*)g_whi + (size_t)idx4 * 2) = hv;
  *(uint2*)((unsigned char*)g_wlo + (size_t)idx4 * 2) = lv;
}

// ============================================================================
// Tensor-core projection: 64 rows x 192 cols (Q|K|V) per CTA, BK=32.
// 256 threads, 8 warps as 4(m:16 rows) x 2(n:96 cols). Split-bf16, 3 terms.
// 64-row CTA keeps regs ~110 and static smem 37.9KB -> 2 CTAs/SM co-resident
// (the 128-row version was register-limited to 1 CTA/SM and latency-bound
// at ~7000 cyc/iter vs a ~2300 cyc tensor floor).
// ============================================================================
__global__ __launch_bounds__(256, 2) void proj_mma_kernel(
    const float* __restrict__ x) {
  __shared__ __align__(16) unsigned char sAhi[64 * kAPitch];  // 5120
  __shared__ __align__(16) unsigned char sAlo[64 * kAPitch];
  __shared__ __align__(16) unsigned char sBhi[3 * 32 * kPitch];  // 13824
  __shared__ __align__(16) unsigned char sBlo[3 * 32 * kPitch];

  const int tid = threadIdx.x;
  const int lane = tid & 31, wid = tid >> 5;
  const int g = lane >> 2, t = lane & 3;
  const int wm = wid & 3;   // row group (16 rows)
  const int wn = wid >> 2;  // col group (96 cols)
  const int row0 = blockIdx.x * 64;
  const uint32_t uAhi = smem_u32(sAhi), uAlo = smem_u32(sAlo);
  const uint32_t uBhi = smem_u32(sBhi), uBlo = smem_u32(sBlo);
  const int lm_r = (lane & 7) + ((lane >> 3) & 1) * 8;
  const int lm_c = (lane & 16) ? 8 : 0;

  float c[12][4] = {};

  // register-prefetch of the first x tile (64x32 fp32 = 512 float4)
  float4 pref[2];
#pragma unroll
  for (int i = 0; i < 2; i++) {
    int idx = tid + i * 256;
    int r = idx >> 3, c4 = (idx & 7) << 2;
    pref[i] = *(const float4*)(x + (size_t)(row0 + r) * kE + c4);
  }

  for (int k0 = 0; k0 < kE; k0 += 32) {
    // store prefetched A tile (split) into smem
#pragma unroll
    for (int i = 0; i < 2; i++) {
      int idx = tid + i * 256;
      int r = idx >> 3, c4 = (idx & 7) << 2;
      unsigned short h[4], l[4];
      split_bf16(pref[i].x, h[0], l[0]); split_bf16(pref[i].y, h[1], l[1]);
      split_bf16(pref[i].z, h[2], l[2]); split_bf16(pref[i].w, h[3], l[3]);
      uint2 hv = {(uint32_t)h[0] | ((uint32_t)h[1] << 16),
                  (uint32_t)h[2] | ((uint32_t)h[3] << 16)};
      uint2 lv = {(uint32_t)l[0] | ((uint32_t)l[1] << 16),
                  (uint32_t)l[2] | ((uint32_t)l[3] << 16)};
      *(uint2*)(sAhi + r * kAPitch + c4 * 2) = hv;
      *(uint2*)(sAlo + r * kAPitch + c4 * 2) = lv;
    }
    // B tiles: 3 x 32 x 64 bf16 hi/lo (pre-split, L2-hot)
#pragma unroll
    for (int i = 0; i < 3; i++) {
      int idx = tid + i * 256;  // 0..767 uint4s
      int w = idx >> 8, rem = idx & 255;
      int r = rem >> 3, cb = (rem & 7) << 4;
      size_t go = ((size_t)w * kE * kD + (size_t)(k0 + r) * kD) * 2 + cb;
      int so = w * 32 * kPitch + r * kPitch + cb;
      *(uint4*)(sBhi + so) = *(const uint4*)((const unsigned char*)g_whi + go);
      *(uint4*)(sBlo + so) = *(const uint4*)((const unsigned char*)g_wlo + go);
    }
    __syncthreads();

    // prefetch next x tile (issued before compute; lands during MMAs)
    if (k0 + 32 < kE) {
#pragma unroll
      for (int i = 0; i < 2; i++) {
        int idx = tid + i * 256;
        int r = idx >> 3, c4 = (idx & 7) << 2;
        pref[i] = *(const float4*)(x + (size_t)(row0 + r) * kE + k0 + 32 + c4);
      }
    }

#pragma unroll
    for (int ks = 0; ks < 2; ks++) {
      uint32_t ah[4], al[4];
      {
        uint32_t off = (uint32_t)((wm * 16 + lm_r) * kAPitch +
                                  (ks * 16 + lm_c) * 2);
        ldsm_x4(ah, uAhi + off);
        ldsm_x4(al, uAlo + off);
      }
#pragma unroll
      for (int nb16 = 0; nb16 < 6; nb16++) {
        int oc16 = wn * 96 + nb16 * 16;
        int w = oc16 >> 6, cin = oc16 & 63;
        uint32_t boff = (uint32_t)(w * 32 * kPitch +
                                   (ks * 16 + lm_r) * kPitch +
                                   (cin + lm_c) * 2);
        uint32_t bh[4], bl[4];
        ldsm_x4_t(bh, uBhi + boff);
        ldsm_x4_t(bl, uBlo + boff);
        float* c0 = c[nb16 * 2];
        float* c1 = c[nb16 * 2 + 1];
        mma_bf16(c0, ah, bh[0], bh[1]);
        mma_bf16(c1, ah, bh[2], bh[3]);
        mma_bf16(c0, ah, bl[0], bl[1]);
        mma_bf16(c1, ah, bl[2], bl[3]);
        mma_bf16(c0, al, bh[0], bh[1]);
        mma_bf16(c1, al, bh[2], bh[3]);
      }
    }
    __syncthreads();
  }

  // Epilogue: split accumulators to bf16 hi/lo global buffers.
#pragma unroll
  for (int nb = 0; nb < 12; nb++) {
    int oc = wn * 96 + nb * 8;
    int w = oc >> 6;
    int cin = (oc & 63) + 2 * t;
    const float scale = (w == 0) ? 0.125f : 1.0f;
    unsigned char* dsthi = (unsigned char*)((w == 0) ? g_qhi
                                            : (w == 1) ? g_khi : g_vhi);
    unsigned char* dstlo = (unsigned char*)((w == 0) ? g_qlo
                                            : (w == 1) ? g_klo : g_vlo);
    size_t rA = row0 + wm * 16 + g;
    size_t rB = rA + 8;
    unsigned short h0, h1, l0, l1;
    split_bf16(c[nb][0] * scale, h0, l0);
    split_bf16(c[nb][1] * scale, h1, l1);
    *(uint32_t*)(dsthi + (rA * kD + cin) * 2) =
        (uint32_t)h0 | ((uint32_t)h1 << 16);
    *(uint32_t*)(dstlo + (rA * kD + cin) * 2) =
        (uint32_t)l0 | ((uint32_t)l1 << 16);
    split_bf16(c[nb][2] * scale, h0, l0);
    split_bf16(c[nb][3] * scale, h1, l1);
    *(uint32_t*)(dsthi + (rB * kD + cin) * 2) =
        (uint32_t)h0 | ((uint32_t)h1 << 16);
    *(uint32_t*)(dstlo + (rB * kD + cin) * 2) =
        (uint32_t)l0 | ((uint32_t)l1 << 16);
  }
}

// ============================================================================
// FA2-style mma.sync attention, causal, bf16-split, fixed-shift softmax.
// One 64-row q-tile per CTA, cp.async double-buffered K/V stages.
// 128 threads, 4 warps; warp w owns 16 q-rows.
//
// SM-balanced static schedule: classic launch maps bid mod 148 -> SM, so
// CTAs i and i+148 share an SM. Work list W sorted heavy-first
// (qt = 31 - widx/8); CTA i takes widx = i for i<148 and widx = 403-i
// otherwise, so SM s hosts W[s] and W[255-s] whose k-tile loads sum to
// ~32.1 for every s (vs 45.5 max under naive heavy-first).
// ============================================================================
__device__ __forceinline__ void attn_issue_tile(uint32_t sbase, int b, int kt,
                                                int tid) {
  const size_t gb = ((size_t)b * kS + (size_t)kt * 64) * kD * 2;  // bytes
  const unsigned char* gkh = (const unsigned char*)g_khi + gb;
  const unsigned char* gkl = (const unsigned char*)g_klo + gb;
  const unsigned char* gvh = (const unsigned char*)g_vhi + gb;
  const unsigned char* gvl = (const unsigned char*)g_vlo + gb;
#pragma unroll
  for (int i = tid; i < 512; i += 128) {
    int r = i >> 3, cb = (i & 7) << 4;
    int so = r * kPitch + cb;
    size_t go = (size_t)r * 128 + cb;
    cp16(sbase + kOffKhi + so, gkh + go);
    cp16(sbase + kOffKlo + so, gkl + go);
    cp16(sbase + kOffVhi + so, gvh + go);
    cp16(sbase + kOffVlo + so, gvl + go);
  }
}

__global__ __launch_bounds__(128, 2) void attn_mma_kernel(float* __restrict__ out) {
  extern __shared__ __align__(16) unsigned char dsm[];
  const uint32_t sb = smem_u32(dsm);

  const int tid = threadIdx.x;
  const int lane = tid & 31, wid = tid >> 5;
  const int g = lane >> 2, t = lane & 3;
  // SM-balanced work index (see header comment).
  const int i = blockIdx.x;
  const int widx = (i < 148) ? i : 403 - i;
  const int qt = 31 - (widx >> 3);
  const int b = widx & 7;
  const int qrow_w = qt * 64 + wid * 16;

  const int lm_r = (lane & 7) + ((lane >> 3) & 1) * 8;
  const int lm_c = (lane & 16) ? 8 : 0;

  // ---- Q fragments (A operand), hi/lo, 4 k-steps of 16.
  uint32_t aqh[4][4], aql[4][4];
  {
    const unsigned char* qh = (const unsigned char*)g_qhi +
                              ((size_t)b * kS + qrow_w + g) * kD * 2 + 4 * t;
    const unsigned char* ql = (const unsigned char*)g_qlo +
                              ((size_t)b * kS + qrow_w + g) * kD * 2 + 4 * t;
#pragma unroll
    for (int ks = 0; ks < 4; ks++) {
      aqh[ks][0] = *(const uint32_t*)(qh + ks * 32);
      aqh[ks][1] = *(const uint32_t*)(qh + 8 * 128 + ks * 32);
      aqh[ks][2] = *(const uint32_t*)(qh + ks * 32 + 16);
      aqh[ks][3] = *(const uint32_t*)(qh + 8 * 128 + ks * 32 + 16);
      aql[ks][0] = *(const uint32_t*)(ql + ks * 32);
      aql[ks][1] = *(const uint32_t*)(ql + 8 * 128 + ks * 32);
      aql[ks][2] = *(const uint32_t*)(ql + ks * 32 + 16);
      aql[ks][3] = *(const uint32_t*)(ql + 8 * 128 + ks * 32 + 16);
    }
  }

  float o[8][4] = {};
  float lsA = 0.0f, lsB = 0.0f;
  const int rowA = qrow_w + g, rowB = rowA + 8;

  // prologue: stage 0 load
  attn_issue_tile(sb, b, 0, tid);
  CP_COMMIT();
  int stage = 0;

  for (int kt = 0; kt <= qt; kt++) {
    const bool has_next = (kt < qt);
    if (has_next) {
      attn_issue_tile(sb + (stage ^ 1) * kStageBytes, b, kt + 1, tid);
      CP_COMMIT();
      CP_WAIT(1);
    } else {
      CP_WAIT(0);
    }
    __syncthreads();

    const uint32_t uKhi = sb + stage * kStageBytes + kOffKhi;
    const uint32_t uKlo = sb + stage * kStageBytes + kOffKlo;
    const uint32_t uVhi = sb + stage * kStageBytes + kOffVhi;
    const uint32_t uVlo = sb + stage * kStageBytes + kOffVlo;

    // ---- S = Qhi*Khi + Qhi*Klo + Qlo*Khi  (per warp: 16x64 tile).
    float sc[8][4] = {};
#pragma unroll
    for (int ks = 0; ks < 4; ks++) {
#pragma unroll
      for (int nbp = 0; nbp < 4; nbp++) {
        uint32_t off = (uint32_t)((nbp * 16 + lm_r) * kPitch +
                                  (ks * 16 + lm_c) * 2);
        uint32_t bh[4], bl[4];
        ldsm_x4(bh, uKhi + off);
        ldsm_x4(bl, uKlo + off);
        mma_bf16(sc[nbp * 2], aqh[ks], bh[0], bh[2]);
        mma_bf16(sc[nbp * 2 + 1], aqh[ks], bh[1], bh[3]);
        mma_bf16(sc[nbp * 2], aqh[ks], bl[0], bl[2]);
        mma_bf16(sc[nbp * 2 + 1], aqh[ks], bl[1], bl[3]);
        mma_bf16(sc[nbp * 2], aql[ks], bh[0], bh[2]);
        mma_bf16(sc[nbp * 2 + 1], aql[ks], bh[1], bh[3]);
      }
    }

    // ---- Softmax (fixed shift) -> P hi/lo A-fragments.
    uint32_t pah[4][4], pal[4][4];
    const bool diag = (kt == qt);
    const int colbase = kt * 64 + 2 * t;
#pragma unroll
    for (int nb = 0; nb < 8; nb++) {
      const int c0 = colbase + nb * 8;
      float p00, p01, p10, p11;
      if (diag) {
        p00 = (c0 <= rowA) ? __expf(sc[nb][0] - kShift) : 0.0f;
        p01 = (c0 + 1 <= rowA) ? __expf(sc[nb][1] - kShift) : 0.0f;
        p10 = (c0 <= rowB) ? __expf(sc[nb][2] - kShift) : 0.0f;
        p11 = (c0 + 1 <= rowB) ? __expf(sc[nb][3] - kShift) : 0.0f;
      } else {
        p00 = __expf(sc[nb][0] - kShift);
        p01 = __expf(sc[nb][1] - kShift);
        p10 = __expf(sc[nb][2] - kShift);
        p11 = __expf(sc[nb][3] - kShift);
      }
      lsA += p00 + p01;
      lsB += p10 + p11;
      __nv_bfloat162 h0 = __floats2bfloat162_rn(p00, p01);
      __nv_bfloat162 h1 = __floats2bfloat162_rn(p10, p11);
      __nv_bfloat162 l0 = __floats2bfloat162_rn(p00 - __low2float(h0),
                                                p01 - __high2float(h0));
      __nv_bfloat162 l1 = __floats2bfloat162_rn(p10 - __low2float(h1),
                                                p11 - __high2float(h1));
      const int ks = nb >> 1;
      if ((nb & 1) == 0) {
        pah[ks][0] = *(uint32_t*)&h0; pah[ks][1] = *(uint32_t*)&h1;
        pal[ks][0] = *(uint32_t*)&l0; pal[ks][1] = *(uint32_t*)&l1;
      } else {
        pah[ks][2] = *(uint32_t*)&h0; pah[ks][3] = *(uint32_t*)&h1;
        pal[ks][2] = *(uint32_t*)&l0; pal[ks][3] = *(uint32_t*)&l1;
      }
    }

    // ---- O += Phi*Vhi + Phi*Vlo + Plo*Vhi  (V via ldmatrix.trans).
#pragma unroll
    for (int ks = 0; ks < 4; ks++) {
#pragma unroll
      for (int nbp = 0; nbp < 4; nbp++) {
        uint32_t off = (uint32_t)((ks * 16 + lm_r) * kPitch +
                                  (nbp * 16 + lm_c) * 2);
        uint32_t bh[4], bl[4];
        ldsm_x4_t(bh, uVhi + off);
        ldsm_x4_t(bl, uVlo + off);
        mma_bf16(o[nbp * 2], pah[ks], bh[0], bh[1]);
        mma_bf16(o[nbp * 2 + 1], pah[ks], bh[2], bh[3]);
        mma_bf16(o[nbp * 2], pah[ks], bl[0], bl[1]);
        mma_bf16(o[nbp * 2 + 1], pah[ks], bl[2], bl[3]);
        mma_bf16(o[nbp * 2], pal[ks], bh[0], bh[1]);
        mma_bf16(o[nbp * 2 + 1], pal[ks], bh[2], bh[3]);
      }
    }
    __syncthreads();  // all warps done with this stage before it is reloaded
    stage ^= 1;
  }

  // ---- Epilogue: quad-reduce l, divide, store.
  lsA += __shfl_xor_sync(0xffffffffu, lsA, 1);
  lsA += __shfl_xor_sync(0xffffffffu, lsA, 2);
  lsB += __shfl_xor_sync(0xffffffffu, lsB, 1);
  lsB += __shfl_xor_sync(0xffffffffu, lsB, 2);
  const float iA = 1.0f / lsA, iB = 1.0f / lsB;
  float* oA = out + ((size_t)b * kS + rowA) * kD;
  float* oB = out + ((size_t)b * kS + rowB) * kD;
#pragma unroll
  for (int nb = 0; nb < 8; nb++) {
    float2 vA = {o[nb][0] * iA, o[nb][1] * iA};
    float2 vB = {o[nb][2] * iB, o[nb][3] * iB};
    *(float2*)(oA + nb * 8 + 2 * t) = vA;
    *(float2*)(oB + nb * 8 + 2 * t) = vB;
  }
}

extern "C" void kernel_launch(void* const* d_in, const int* in_sizes, int n_in,
                              void* d_out, int out_size) {
  const float* x = (const float*)d_in[0];
  const float* Wq = (const float*)d_in[1];
  const float* Wk = (const float*)d_in[2];
  const float* Wv = (const float*)d_in[3];
  float* out = (float*)d_out;

  const int attn_smem = 2 * kStageBytes;  // 73728
  cudaFuncSetAttribute(attn_mma_kernel,
                       cudaFuncAttributeMaxDynamicSharedMemorySize, attn_smem);

  split_w_kernel<<<192, 256>>>(Wq, Wk, Wv);
  proj_mma_kernel<<<kRows / 64, 256>>>(x);
  attn_mma_kernel<<<256, 128, attn_smem>>>(out);
}

// round 13
// speedup vs baseline: 1.0326x; 1.0326x over previous
#include <cuda_runtime.h>
#include <cuda_bf16.h>
#include <cstdint>
#include <math.h>

// ============================================================================
// Problem constants
// ============================================================================
namespace {
constexpr int kE = 1024;
constexpr int kD = 64;
constexpr int kB = 8;
constexpr int kS = 2048;
constexpr int kRows = kB * kS;  // 16384
constexpr float kShift = 16.0f;  // fixed softmax shift; scores ~N(0,1)
constexpr int kPitch = 144;      // smem K/V/B row pitch bytes (64 bf16 + pad)
constexpr int kAPitch = 80;      // proj A smem pitch bytes; MUST be 16B mult
                                 // (ldmatrix row addrs are 128-bit aligned)
// attn stage layout (bytes)
constexpr int kStageBytes = 4 * 64 * kPitch;  // 36864
constexpr int kOffKhi = 0, kOffKlo = 9216, kOffVhi = 18432, kOffVlo = 27648;
// proj dynamic smem layout (bytes)
constexpr int kPAhi = 0;                       // 128*80 = 10240
constexpr int kPAlo = 10240;
constexpr int kPB0 = 20480;                    // B stages: hi|lo per stage
constexpr int kPBStage = 2 * 3 * 32 * kPitch;  // 27648
constexpr int kPBLoOff = 3 * 32 * kPitch;      // 13824
constexpr int kProjSmem = kPB0 + 2 * kPBStage; // 75776
}

// bf16 split operands (hi + lo ~= fp32). 16B-aligned: accessed with
// uint4 / cp.async.16.
__device__ __align__(16) __nv_bfloat16 g_qhi[kRows * kD];
__device__ __align__(16) __nv_bfloat16 g_qlo[kRows * kD];
__device__ __align__(16) __nv_bfloat16 g_khi[kRows * kD];
__device__ __align__(16) __nv_bfloat16 g_klo[kRows * kD];
__device__ __align__(16) __nv_bfloat16 g_vhi[kRows * kD];
__device__ __align__(16) __nv_bfloat16 g_vlo[kRows * kD];
// pre-split weights, layout [w][k][n], w in {q,k,v}
__device__ __align__(16) __nv_bfloat16 g_whi[3 * kE * kD];
__device__ __align__(16) __nv_bfloat16 g_wlo[3 * kE * kD];

__device__ __forceinline__ void split_bf16(float x, unsigned short& h,
                                           unsigned short& l) {
  __nv_bfloat16 bh = __float2bfloat16_rn(x);
  h = __bfloat16_as_ushort(bh);
  float r = x - __bfloat162float(bh);
  l = __bfloat16_as_ushort(__float2bfloat16_rn(r));
}

__device__ __forceinline__ uint32_t smem_u32(const void* p) {
  uint32_t a;
  asm("{ .reg .u64 t; cvta.to.shared.u64 t, %1; cvt.u32.u64 %0, t; }"
      : "=r"(a) : "l"(p));
  return a;
}

// mma.sync m16n8k16 row.col f32 += bf16*bf16
__device__ __forceinline__ void mma_bf16(float* c, const uint32_t* a,
                                         uint32_t b0, uint32_t b1) {
  asm volatile(
      "mma.sync.aligned.m16n8k16.row.col.f32.bf16.bf16.f32 "
      "{%0,%1,%2,%3}, {%4,%5,%6,%7}, {%8,%9}, {%0,%1,%2,%3};\n"
      : "+f"(c[0]), "+f"(c[1]), "+f"(c[2]), "+f"(c[3])
      : "r"(a[0]), "r"(a[1]), "r"(a[2]), "r"(a[3]), "r"(b0), "r"(b1));
}
__device__ __forceinline__ void ldsm_x4(uint32_t* r, uint32_t addr) {
  asm volatile("ldmatrix.sync.aligned.m8n8.x4.shared.b16 {%0,%1,%2,%3}, [%4];"
               : "=r"(r[0]), "=r"(r[1]), "=r"(r[2]), "=r"(r[3]) : "r"(addr));
}
__device__ __forceinline__ void ldsm_x4_t(uint32_t* r, uint32_t addr) {
  asm volatile(
      "ldmatrix.sync.aligned.m8n8.x4.trans.shared.b16 {%0,%1,%2,%3}, [%4];"
      : "=r"(r[0]), "=r"(r[1]), "=r"(r[2]), "=r"(r[3]) : "r"(addr));
}
__device__ __forceinline__ void cp16(uint32_t s, const void* g) {
  asm volatile("cp.async.cg.shared.global [%0], [%1], 16;" ::"r"(s), "l"(g));
}
#define CP_COMMIT() asm volatile("cp.async.commit_group;" ::: "memory")
#define CP_WAIT(n) asm volatile("cp.async.wait_group %0;" ::"n"(n) : "memory")

// ============================================================================
// One-time W split: [w][k][n] fp32 -> bf16 hi/lo.
// ============================================================================
__global__ __launch_bounds__(256) void split_w_kernel(
    const float* __restrict__ Wq, const float* __restrict__ Wk,
    const float* __restrict__ Wv) {
  int idx4 = (blockIdx.x * 256 + threadIdx.x) * 4;  // grid 192 -> 196608 elems
  int w = idx4 >> 16, rem = idx4 & 65535;
  const float* Wp = (w == 0) ? Wq : (w == 1) ? Wk : Wv;
  float4 v = *(const float4*)(Wp + rem);
  unsigned short h[4], l[4];
  split_bf16(v.x, h[0], l[0]); split_bf16(v.y, h[1], l[1]);
  split_bf16(v.z, h[2], l[2]); split_bf16(v.w, h[3], l[3]);
  uint2 hv = {(uint32_t)h[0] | ((uint32_t)h[1] << 16),
              (uint32_t)h[2] | ((uint32_t)h[3] << 16)};
  uint2 lv = {(uint32_t)l[0] | ((uint32_t)l[1] << 16),
              (uint32_t)l[2] | ((uint32_t)l[3] << 16)};
  *(uint2*)((unsigned char*)g_whi + (size_t)idx4 * 2) = hv;
  *(uint2*)((unsigned char*)g_wlo + (size_t)idx4 * 2) = lv;
}

// ============================================================================
// Tensor-core projection: 128 rows x 192 cols (Q|K|V) per CTA, BK=32.
// 256 threads, 8 warps as 4(m:32 rows) x 2(n:96 cols). Split-bf16, 3 terms.
// B tiles cp.async double-buffered (R11 exposed ~500 cyc/iter of sync B LDG);
// A tile register-prefetched fp32 + split->STS, single smem buffer.
// ============================================================================
__global__ __launch_bounds__(256) void proj_mma_kernel(const float* __restrict__ x) {
  extern __shared__ __align__(16) unsigned char psm[];
  const uint32_t sb = smem_u32(psm);
  const uint32_t uAhi = sb + kPAhi, uAlo = sb + kPAlo;

  const int tid = threadIdx.x;
  const int lane = tid & 31, wid = tid >> 5;
  const int g = lane >> 2, t = lane & 3;
  const int wm = wid & 3;   // row group (32 rows)
  const int wn = wid >> 2;  // col group (96 cols)
  const int row0 = blockIdx.x * 128;
  const int lm_r = (lane & 7) + ((lane >> 3) & 1) * 8;
  const int lm_c = (lane & 16) ? 8 : 0;

  float c[2][12][4] = {};

  // register-prefetch of the first x tile
  float4 pref[4];
#pragma unroll
  for (int i = 0; i < 4; i++) {
    int idx = tid + i * 256;
    int r = idx >> 3, c4 = (idx & 7) << 2;
    pref[i] = *(const float4*)(x + (size_t)(row0 + r) * kE + c4);
  }

  // prologue: B stage 0 via cp.async
  auto issue_b = [&](int stage, int k0) {
    const uint32_t bs = sb + kPB0 + stage * kPBStage;
#pragma unroll
    for (int i = 0; i < 3; i++) {
      int idx = tid + i * 256;  // 0..767 uint4s
      int w = idx >> 8, rem = idx & 255;
      int r = rem >> 3, cb = (rem & 7) << 4;
      size_t go = ((size_t)w * kE * kD + (size_t)(k0 + r) * kD) * 2 + cb;
      uint32_t so = (uint32_t)(w * 32 * kPitch + r * kPitch + cb);
      cp16(bs + so, (const unsigned char*)g_whi + go);
      cp16(bs + kPBLoOff + so, (const unsigned char*)g_wlo + go);
    }
  };
  issue_b(0, 0);
  CP_COMMIT();
  int stage = 0;

  for (int k0 = 0; k0 < kE; k0 += 32) {
    const bool has_next = (k0 + 32 < kE);
    // issue next B tile first (maximum overlap)
    if (has_next) {
      issue_b(stage ^ 1, k0 + 32);
      CP_COMMIT();
    }
    // store prefetched A tile (split) into smem
#pragma unroll
    for (int i = 0; i < 4; i++) {
      int idx = tid + i * 256;
      int r = idx >> 3, c4 = (idx & 7) << 2;
      unsigned short h[4], l[4];
      split_bf16(pref[i].x, h[0], l[0]); split_bf16(pref[i].y, h[1], l[1]);
      split_bf16(pref[i].z, h[2], l[2]); split_bf16(pref[i].w, h[3], l[3]);
      uint2 hv = {(uint32_t)h[0] | ((uint32_t)h[1] << 16),
                  (uint32_t)h[2] | ((uint32_t)h[3] << 16)};
      uint2 lv = {(uint32_t)l[0] | ((uint32_t)l[1] << 16),
                  (uint32_t)l[2] | ((uint32_t)l[3] << 16)};
      *(uint2*)(psm + kPAhi + r * kAPitch + c4 * 2) = hv;
      *(uint2*)(psm + kPAlo + r * kAPitch + c4 * 2) = lv;
    }
    if (has_next) {
      CP_WAIT(1);  // current stage complete; next in flight
    } else {
      CP_WAIT(0);
    }
    __syncthreads();

    // prefetch next x tile (lands during MMAs)
    if (has_next) {
#pragma unroll
      for (int i = 0; i < 4; i++) {
        int idx = tid + i * 256;
        int r = idx >> 3, c4 = (idx & 7) << 2;
        pref[i] = *(const float4*)(x + (size_t)(row0 + r) * kE + k0 + 32 + c4);
      }
    }

    const uint32_t uBhi = sb + kPB0 + stage * kPBStage;
    const uint32_t uBlo = uBhi + kPBLoOff;
#pragma unroll
    for (int ks = 0; ks < 2; ks++) {
      uint32_t ah[2][4], al[2][4];
#pragma unroll
      for (int mb = 0; mb < 2; mb++) {
        uint32_t off = (uint32_t)((wm * 32 + mb * 16 + lm_r) * kAPitch +
                                  (ks * 16 + lm_c) * 2);
        ldsm_x4(ah[mb], uAhi + off);
        ldsm_x4(al[mb], uAlo + off);
      }
#pragma unroll
      for (int nb16 = 0; nb16 < 6; nb16++) {
        int oc16 = wn * 96 + nb16 * 16;
        int w = oc16 >> 6, cin = oc16 & 63;
        uint32_t boff = (uint32_t)(w * 32 * kPitch +
                                   (ks * 16 + lm_r) * kPitch +
                                   (cin + lm_c) * 2);
        uint32_t bh[4], bl[4];
        ldsm_x4_t(bh, uBhi + boff);
        ldsm_x4_t(bl, uBlo + boff);
#pragma unroll
        for (int mb = 0; mb < 2; mb++) {
          float* c0 = c[mb][nb16 * 2];
          float* c1 = c[mb][nb16 * 2 + 1];
          mma_bf16(c0, ah[mb], bh[0], bh[1]);
          mma_bf16(c1, ah[mb], bh[2], bh[3]);
          mma_bf16(c0, ah[mb], bl[0], bl[1]);
          mma_bf16(c1, ah[mb], bl[2], bl[3]);
          mma_bf16(c0, al[mb], bh[0], bh[1]);
          mma_bf16(c1, al[mb], bh[2], bh[3]);
        }
      }
    }
    __syncthreads();  // protect A buffer + consumed B stage before overwrite
    stage ^= 1;
  }

  // Epilogue: split accumulators to bf16 hi/lo global buffers.
#pragma unroll
  for (int mb = 0; mb < 2; mb++) {
#pragma unroll
    for (int nb = 0; nb < 12; nb++) {
      int oc = wn * 96 + nb * 8;
      int w = oc >> 6;
      int cin = (oc & 63) + 2 * t;
      const float scale = (w == 0) ? 0.125f : 1.0f;
      unsigned char* dsthi = (unsigned char*)((w == 0) ? g_qhi
                                              : (w == 1) ? g_khi : g_vhi);
      unsigned char* dstlo = (unsigned char*)((w == 0) ? g_qlo
                                              : (w == 1) ? g_klo : g_vlo);
      size_t rA = row0 + wm * 32 + mb * 16 + g;
      size_t rB = rA + 8;
      unsigned short h0, h1, l0, l1;
      split_bf16(c[mb][nb][0] * scale, h0, l0);
      split_bf16(c[mb][nb][1] * scale, h1, l1);
      *(uint32_t*)(dsthi + (rA * kD + cin) * 2) =
          (uint32_t)h0 | ((uint32_t)h1 << 16);
      *(uint32_t*)(dstlo + (rA * kD + cin) * 2) =
          (uint32_t)l0 | ((uint32_t)l1 << 16);
      split_bf16(c[mb][nb][2] * scale, h0, l0);
      split_bf16(c[mb][nb][3] * scale, h1, l1);
      *(uint32_t*)(dsthi + (rB * kD + cin) * 2) =
          (uint32_t)h0 | ((uint32_t)h1 << 16);
      *(uint32_t*)(dstlo + (rB * kD + cin) * 2) =
          (uint32_t)l0 | ((uint32_t)l1 << 16);
    }
  }
}

// ============================================================================
// FA2-style mma.sync attention, causal, bf16-split, fixed-shift softmax.
// One 64-row q-tile per CTA, cp.async double-buffered K/V stages.
// 128 threads, 4 warps; warp w owns 16 q-rows.
//
// SM-balanced static schedule: classic launch maps bid mod 148 -> SM, so
// CTAs i and i+148 share an SM. Work list W sorted heavy-first
// (qt = 31 - widx/8); CTA i takes widx = i for i<148 and widx = 403-i
// otherwise, so SM s hosts W[s] and W[255-s] whose k-tile loads sum to
// ~32.1 for every s (vs 45.5 max under naive heavy-first).
// ============================================================================
__device__ __forceinline__ void attn_issue_tile(uint32_t sbase, int b, int kt,
                                                int tid) {
  const size_t gb = ((size_t)b * kS + (size_t)kt * 64) * kD * 2;  // bytes
  const unsigned char* gkh = (const unsigned char*)g_khi + gb;
  const unsigned char* gkl = (const unsigned char*)g_klo + gb;
  const unsigned char* gvh = (const unsigned char*)g_vhi + gb;
  const unsigned char* gvl = (const unsigned char*)g_vlo + gb;
#pragma unroll
  for (int i = tid; i < 512; i += 128) {
    int r = i >> 3, cb = (i & 7) << 4;
    int so = r * kPitch + cb;
    size_t go = (size_t)r * 128 + cb;
    cp16(sbase + kOffKhi + so, gkh + go);
    cp16(sbase + kOffKlo + so, gkl + go);
    cp16(sbase + kOffVhi + so, gvh + go);
    cp16(sbase + kOffVlo + so, gvl + go);
  }
}

__global__ __launch_bounds__(128, 2) void attn_mma_kernel(float* __restrict__ out) {
  extern __shared__ __align__(16) unsigned char dsm[];
  const uint32_t sb = smem_u32(dsm);

  const int tid = threadIdx.x;
  const int lane = tid & 31, wid = tid >> 5;
  const int g = lane >> 2, t = lane & 3;
  // SM-balanced work index (see header comment).
  const int i = blockIdx.x;
  const int widx = (i < 148) ? i : 403 - i;
  const int qt = 31 - (widx >> 3);
  const int b = widx & 7;
  const int qrow_w = qt * 64 + wid * 16;

  const int lm_r = (lane & 7) + ((lane >> 3) & 1) * 8;
  const int lm_c = (lane & 16) ? 8 : 0;

  // ---- Q fragments (A operand), hi/lo, 4 k-steps of 16.
  uint32_t aqh[4][4], aql[4][4];
  {
    const unsigned char* qh = (const unsigned char*)g_qhi +
                              ((size_t)b * kS + qrow_w + g) * kD * 2 + 4 * t;
    const unsigned char* ql = (const unsigned char*)g_qlo +
                              ((size_t)b * kS + qrow_w + g) * kD * 2 + 4 * t;
#pragma unroll
    for (int ks = 0; ks < 4; ks++) {
      aqh[ks][0] = *(const uint32_t*)(qh + ks * 32);
      aqh[ks][1] = *(const uint32_t*)(qh + 8 * 128 + ks * 32);
      aqh[ks][2] = *(const uint32_t*)(qh + ks * 32 + 16);
      aqh[ks][3] = *(const uint32_t*)(qh + 8 * 128 + ks * 32 + 16);
      aql[ks][0] = *(const uint32_t*)(ql + ks * 32);
      aql[ks][1] = *(const uint32_t*)(ql + 8 * 128 + ks * 32);
      aql[ks][2] = *(const uint32_t*)(ql + ks * 32 + 16);
      aql[ks][3] = *(const uint32_t*)(ql + 8 * 128 + ks * 32 + 16);
    }
  }

  float o[8][4] = {};
  float lsA = 0.0f, lsB = 0.0f;
  const int rowA = qrow_w + g, rowB = rowA + 8;

  // prologue: stage 0 load
  attn_issue_tile(sb, b, 0, tid);
  CP_COMMIT();
  int stage = 0;

  for (int kt = 0; kt <= qt; kt++) {
    const bool has_next = (kt < qt);
    if (has_next) {
      attn_issue_tile(sb + (stage ^ 1) * kStageBytes, b, kt + 1, tid);
      CP_COMMIT();
      CP_WAIT(1);
    } else {
      CP_WAIT(0);
    }
    __syncthreads();

    const uint32_t uKhi = sb + stage * kStageBytes + kOffKhi;
    const uint32_t uKlo = sb + stage * kStageBytes + kOffKlo;
    const uint32_t uVhi = sb + stage * kStageBytes + kOffVhi;
    const uint32_t uVlo = sb + stage * kStageBytes + kOffVlo;

    // ---- S = Qhi*Khi + Qhi*Klo + Qlo*Khi  (per warp: 16x64 tile).
    float sc[8][4] = {};
#pragma unroll
    for (int ks = 0; ks < 4; ks++) {
#pragma unroll
      for (int nbp = 0; nbp < 4; nbp++) {
        uint32_t off = (uint32_t)((nbp * 16 + lm_r) * kPitch +
                                  (ks * 16 + lm_c) * 2);
        uint32_t bh[4], bl[4];
        ldsm_x4(bh, uKhi + off);
        ldsm_x4(bl, uKlo + off);
        mma_bf16(sc[nbp * 2], aqh[ks], bh[0], bh[2]);
        mma_bf16(sc[nbp * 2 + 1], aqh[ks], bh[1], bh[3]);
        mma_bf16(sc[nbp * 2], aqh[ks], bl[0], bl[2]);
        mma_bf16(sc[nbp * 2 + 1], aqh[ks], bl[1], bl[3]);
        mma_bf16(sc[nbp * 2], aql[ks], bh[0], bh[2]);
        mma_bf16(sc[nbp * 2 + 1], aql[ks], bh[1], bh[3]);
      }
    }

    // ---- Softmax (fixed shift) -> P hi/lo A-fragments.
    uint32_t pah[4][4], pal[4][4];
    const bool diag = (kt == qt);
    const int colbase = kt * 64 + 2 * t;
#pragma unroll
    for (int nb = 0; nb < 8; nb++) {
      const int c0 = colbase + nb * 8;
      float p00, p01, p10, p11;
      if (diag) {
        p00 = (c0 <= rowA) ? __expf(sc[nb][0] - kShift) : 0.0f;
        p01 = (c0 + 1 <= rowA) ? __expf(sc[nb][1] - kShift) : 0.0f;
        p10 = (c0 <= rowB) ? __expf(sc[nb][2] - kShift) : 0.0f;
        p11 = (c0 + 1 <= rowB) ? __expf(sc[nb][3] - kShift) : 0.0f;
      } else {
        p00 = __expf(sc[nb][0] - kShift);
        p01 = __expf(sc[nb][1] - kShift);
        p10 = __expf(sc[nb][2] - kShift);
        p11 = __expf(sc[nb][3] - kShift);
      }
      lsA += p00 + p01;
      lsB += p10 + p11;
      __nv_bfloat162 h0 = __floats2bfloat162_rn(p00, p01);
      __nv_bfloat162 h1 = __floats2bfloat162_rn(p10, p11);
      __nv_bfloat162 l0 = __floats2bfloat162_rn(p00 - __low2float(h0),
                                                p01 - __high2float(h0));
      __nv_bfloat162 l1 = __floats2bfloat162_rn(p10 - __low2float(h1),
                                                p11 - __high2float(h1));
      const int ks = nb >> 1;
      if ((nb & 1) == 0) {
        pah[ks][0] = *(uint32_t*)&h0; pah[ks][1] = *(uint32_t*)&h1;
        pal[ks][0] = *(uint32_t*)&l0; pal[ks][1] = *(uint32_t*)&l1;
      } else {
        pah[ks][2] = *(uint32_t*)&h0; pah[ks][3] = *(uint32_t*)&h1;
        pal[ks][2] = *(uint32_t*)&l0; pal[ks][3] = *(uint32_t*)&l1;
      }
    }

    // ---- O += Phi*Vhi + Phi*Vlo + Plo*Vhi  (V via ldmatrix.trans).
#pragma unroll
    for (int ks = 0; ks < 4; ks++) {
#pragma unroll
      for (int nbp = 0; nbp < 4; nbp++) {
        uint32_t off = (uint32_t)((ks * 16 + lm_r) * kPitch +
                                  (nbp * 16 + lm_c) * 2);
        uint32_t bh[4], bl[4];
        ldsm_x4_t(bh, uVhi + off);
        ldsm_x4_t(bl, uVlo + off);
        mma_bf16(o[nbp * 2], pah[ks], bh[0], bh[1]);
        mma_bf16(o[nbp * 2 + 1], pah[ks], bh[2], bh[3]);
        mma_bf16(o[nbp * 2], pah[ks], bl[0], bl[1]);
        mma_bf16(o[nbp * 2 + 1], pah[ks], bl[2], bl[3]);
        mma_bf16(o[nbp * 2], pal[ks], bh[0], bh[1]);
        mma_bf16(o[nbp * 2 + 1], pal[ks], bh[2], bh[3]);
      }
    }
    __syncthreads();  // all warps done with this stage before it is reloaded
    stage ^= 1;
  }

  // ---- Epilogue: quad-reduce l, divide, store.
  lsA += __shfl_xor_sync(0xffffffffu, lsA, 1);
  lsA += __shfl_xor_sync(0xffffffffu, lsA, 2);
  lsB += __shfl_xor_sync(0xffffffffu, lsB, 1);
  lsB += __shfl_xor_sync(0xffffffffu, lsB, 2);
  const float iA = 1.0f / lsA, iB = 1.0f / lsB;
  float* oA = out + ((size_t)b * kS + rowA) * kD;
  float* oB = out + ((size_t)b * kS + rowB) * kD;
#pragma unroll
  for (int nb = 0; nb < 8; nb++) {
    float2 vA = {o[nb][0] * iA, o[nb][1] * iA};
    float2 vB = {o[nb][2] * iB, o[nb][3] * iB};
    *(float2*)(oA + nb * 8 + 2 * t) = vA;
    *(float2*)(oB + nb * 8 + 2 * t) = vB;
  }
}

extern "C" void kernel_launch(void* const* d_in, const int* in_sizes, int n_in,
                              void* d_out, int out_size) {
  const float* x = (const float*)d_in[0];
  const float* Wq = (const float*)d_in[1];
  const float* Wk = (const float*)d_in[2];
  const float* Wv = (const float*)d_in[3];
  float* out = (float*)d_out;

  const int attn_smem = 2 * kStageBytes;  // 73728
  cudaFuncSetAttribute(attn_mma_kernel,
                       cudaFuncAttributeMaxDynamicSharedMemorySize, attn_smem);
  cudaFuncSetAttribute(proj_mma_kernel,
                       cudaFuncAttributeMaxDynamicSharedMemorySize, kProjSmem);

  split_w_kernel<<<192, 256>>>(Wq, Wk, Wv);
  proj_mma_kernel<<<kRows / 128, 256, kProjSmem>>>(x);
  attn_mma_kernel<<<256, 128, attn_smem>>>(out);
}